// round 4
// baseline (speedup 1.0000x reference)
#include <cuda_runtime.h>
#include <math.h>

#define SIZE 512
#define NB 16
#define L 1534
#define NC 16
#define O1 1023
#define O2 512
#define BN_EPS 1e-3f

// ---------------- scratch (no allocations allowed) ----------------
// Shift-replicated h1: g_h1a[m][b*1024 + j] = h1[b][j + m]   (m = 0..3)
__device__ float g_h1a[4][NB * 1024];
__device__ float g_h2[NB * O2];              // [b][o2]

// packed fp32x2 FMA (sm_103a FFMA2 path)
__device__ __forceinline__ void ffma2(unsigned long long &acc,
                                      unsigned long long a,
                                      unsigned long long w) {
    asm("fma.rn.f32x2 %0, %1, %2, %0;" : "+l"(acc) : "l"(a), "l"(w));
}

// =====================================================================
// Kernel 1: full stage-1 in one pass -> h1 (bias + ELU fused), written
// to 4 shift-replicated arrays for aligned stage-2 reads.
// grid (64 o-tiles, 2 batch-halves), block 256:
//   g  = t & 31      : 32-way split of the 527-row window (d = g + 32*i)
//   oq = (t>>5) & 3  : o-quad (4 o per thread -> 16 o per block)
//   bh = t >> 7      : batch quad (4 b per thread -> 8 b per block)
// Interior iterations i=1..15 are completely predicate-free.
// =====================================================================
__global__ __launch_bounds__(256) void k_stage1(const float* __restrict__ x,
                                                const float* __restrict__ W1,
                                                const float* __restrict__ b1) {
    const int t  = threadIdx.x;
    const int g  = t & 31;
    const int oq = (t >> 5) & 3;
    const int bh = t >> 7;
    const int o0 = blockIdx.x * 16;
    const int b0 = blockIdx.y * 8 + bh * 4;     // first of this thread's 4 batches

    unsigned long long acc[4][4];
    #pragma unroll
    for (int oo = 0; oo < 4; oo++)
        #pragma unroll
        for (int b = 0; b < 4; b++) acc[oo][b] = 0ull;

    const float* xbase = x + (b0 * L + o0) * NC;
    const float* wbase[4];
    #pragma unroll
    for (int oo = 0; oo < 4; oo++) {
        const int oloc = oq * 4 + oo;
        const int og   = min(o0 + oloc, O1 - 1);   // clamp: o=1023 is a dead output
        wbase[oo] = W1 + (og * SIZE - oloc) * NC;  // +d*NC below yields s_loc*NC
    }

    // ---- i = 0 : d in [0,32), weight valid iff g >= oloc ----
    {
        const int d = g;
        const float* xp = xbase + d * NC;
        #pragma unroll
        for (int h = 0; h < 4; h++) {
            ulonglong2 w[4];
            #pragma unroll
            for (int oo = 0; oo < 4; oo++) {
                ulonglong2 wv; wv.x = 0ull; wv.y = 0ull;
                if (g >= oq * 4 + oo)
                    wv = *reinterpret_cast<const ulonglong2*>(wbase[oo] + d * NC + h * 4);
                w[oo] = wv;
            }
            #pragma unroll
            for (int b = 0; b < 4; b++) {
                ulonglong2 xv = *reinterpret_cast<const ulonglong2*>(xp + b * (L * NC) + h * 4);
                #pragma unroll
                for (int oo = 0; oo < 4; oo++) {
                    ffma2(acc[oo][b], xv.x, w[oo].x);
                    ffma2(acc[oo][b], xv.y, w[oo].y);
                }
            }
        }
    }

    // ---- i = 1..15 : fully valid, no predicates ----
    #pragma unroll 5
    for (int i = 1; i < 16; i++) {
        const int d = g + (i << 5);
        const float* xp = xbase + d * NC;
        #pragma unroll
        for (int h = 0; h < 4; h++) {
            ulonglong2 w[4];
            #pragma unroll
            for (int oo = 0; oo < 4; oo++)
                w[oo] = *reinterpret_cast<const ulonglong2*>(wbase[oo] + d * NC + h * 4);
            #pragma unroll
            for (int b = 0; b < 4; b++) {
                ulonglong2 xv = *reinterpret_cast<const ulonglong2*>(xp + b * (L * NC) + h * 4);
                #pragma unroll
                for (int oo = 0; oo < 4; oo++) {
                    ffma2(acc[oo][b], xv.x, w[oo].x);
                    ffma2(acc[oo][b], xv.y, w[oo].y);
                }
            }
        }
    }

    // ---- i = 16 : d in [512,527), weight valid iff oloc > g (so g<15 only) ----
    if (g < 15) {
        const int d = g + 512;
        const int r = min(o0 + d, L - 1);   // row 1534 feeds only the dead output
        const float* xp = x + (b0 * L + r) * NC;
        #pragma unroll
        for (int h = 0; h < 4; h++) {
            ulonglong2 w[4];
            #pragma unroll
            for (int oo = 0; oo < 4; oo++) {
                ulonglong2 wv; wv.x = 0ull; wv.y = 0ull;
                if (oq * 4 + oo > g)
                    wv = *reinterpret_cast<const ulonglong2*>(wbase[oo] + d * NC + h * 4);
                w[oo] = wv;
            }
            #pragma unroll
            for (int b = 0; b < 4; b++) {
                ulonglong2 xv = *reinterpret_cast<const ulonglong2*>(xp + b * (L * NC) + h * 4);
                #pragma unroll
                for (int oo = 0; oo < 4; oo++) {
                    ffma2(acc[oo][b], xv.x, w[oo].x);
                    ffma2(acc[oo][b], xv.y, w[oo].y);
                }
            }
        }
    }

    // ---- cross-thread (g) reduction, conflict-free (stride 133: 5 mod 32) ----
    __shared__ float sr[2][32 * 133];
    #pragma unroll
    for (int oo = 0; oo < 4; oo++)
        #pragma unroll
        for (int b = 0; b < 4; b++) {
            float2 v = *reinterpret_cast<float2*>(&acc[oo][b]);
            const int p = (oq * 4 + oo) * 8 + bh * 4 + b;   // 0..127
            sr[0][g * 133 + p] = v.x;
            sr[1][g * 133 + p] = v.y;
        }
    __syncthreads();

    if (t < 128) {
        float s = 0.f;
        #pragma unroll
        for (int gg = 0; gg < 32; gg++)
            s += sr[0][gg * 133 + t] + sr[1][gg * 133 + t];
        const int o = o0 + (t >> 3);
        const int b = blockIdx.y * 8 + (t & 7);
        if (o < O1) {
            s += b1[o];
            const float v = (s > 0.f) ? s : expm1f(s);   // ELU(alpha=1)
            #pragma unroll
            for (int m = 0; m < 4; m++)
                if (o >= m) g_h1a[m][b * 1024 + (o - m)] = v;
        }
    }
}

// =====================================================================
// Kernel 2: stage-2  h2[b,o2] = sum_s h1[b,o2+s] * W2[o2,s] + b2[o2]
// grid 64 (8 o2 per block), block 256 (32-way s split, 16 s each).
// Aligned float4 h1 reads via the shift-replicated array A_{o2&3}.
// =====================================================================
__global__ __launch_bounds__(256) void k_stage2(const float* __restrict__ W2,
                                                const float* __restrict__ b2) {
    const int t  = threadIdx.x;
    const int l  = t & 31;
    const int ol = t >> 5;
    const int o2 = blockIdx.x * 8 + ol;
    const int m  = o2 & 3;
    const int base = o2 & ~3;

    const float* hp = g_h1a[m] + base + l * 16;   // h1[o2 + s] = A_m[base + s]
    const float* wp = W2 + o2 * SIZE + l * 16;

    unsigned long long acc[NB];
    #pragma unroll
    for (int b = 0; b < NB; b++) acc[b] = 0ull;

    #pragma unroll
    for (int s4 = 0; s4 < 4; s4++) {
        ulonglong2 wv = *reinterpret_cast<const ulonglong2*>(wp + s4 * 4);
        #pragma unroll
        for (int b = 0; b < NB; b++) {
            ulonglong2 xv = *reinterpret_cast<const ulonglong2*>(hp + b * 1024 + s4 * 4);
            ffma2(acc[b], xv.x, wv.x);
            ffma2(acc[b], xv.y, wv.y);
        }
    }

    __shared__ float sr[2][32 * 133];
    #pragma unroll
    for (int b = 0; b < NB; b++) {
        float2 v = *reinterpret_cast<float2*>(&acc[b]);
        const int p = ol * 16 + b;     // 0..127
        sr[0][l * 133 + p] = v.x;
        sr[1][l * 133 + p] = v.y;
    }
    __syncthreads();

    if (t < 128) {
        float s = 0.f;
        #pragma unroll
        for (int gg = 0; gg < 32; gg++)
            s += sr[0][gg * 133 + t] + sr[1][gg * 133 + t];
        const int o2g = blockIdx.x * 8 + (t >> 4);
        const int b   = t & 15;
        g_h2[b * O2 + o2g] = s + b2[o2g];
    }
}

// =====================================================================
// Kernel 3: gate g[b] = (h2.Wl + bl) * sigmoid(h2.Ws + bs), then
// out[b,l,c] = ((xpad + g) - mean)*rsqrt(var+eps)*gamma + beta
// grid (16 b, 12 row-chunks of 128), block 256. Gate recomputed per block.
// =====================================================================
__global__ __launch_bounds__(256) void k_out(const float* __restrict__ x,
                                             const float* __restrict__ Wl,
                                             const float* __restrict__ bl,
                                             const float* __restrict__ Ws,
                                             const float* __restrict__ bs,
                                             const float* __restrict__ gamma,
                                             const float* __restrict__ beta,
                                             const float* __restrict__ mean,
                                             const float* __restrict__ var,
                                             float* __restrict__ out) {
    const int b  = blockIdx.x;
    const int cb = blockIdx.y;
    const int t  = threadIdx.x;

    // gate reduction (512-elem dots, 2 elems/thread)
    float h2a = g_h2[b * O2 + t];
    float h2b = g_h2[b * O2 + 256 + t];
    float aL = h2a * Wl[t] + h2b * Wl[256 + t];
    float aS = h2a * Ws[t] + h2b * Ws[256 + t];
    #pragma unroll
    for (int off = 16; off; off >>= 1) {
        aL += __shfl_down_sync(0xffffffffu, aL, off);
        aS += __shfl_down_sync(0xffffffffu, aS, off);
    }
    __shared__ float rL[8], rS[8];
    __shared__ float sa[16], sd[16];
    __shared__ float gsh;
    if ((t & 31) == 0) { rL[t >> 5] = aL; rS[t >> 5] = aS; }
    __syncthreads();
    if (t == 0) {
        float sL = 0.f, sS = 0.f;
        #pragma unroll
        for (int j = 0; j < 8; j++) { sL += rL[j]; sS += rS[j]; }
        sL += bl[0]; sS += bs[0];
        gsh = sL * (1.f / (1.f + expf(-sS)));
    }
    __syncthreads();
    if (t < 16) {
        float sc = gamma[t] * rsqrtf(var[t] + BN_EPS);
        sa[t] = sc;
        sd[t] = beta[t] - mean[t] * sc + gsh * sc;   // folds gate + BN shift
    }
    __syncthreads();

    const int row0 = cb * 128;
    const int rows = min(128, 1535 - row0);
    const float4* x4 = reinterpret_cast<const float4*>(x);
    float4* o4 = reinterpret_cast<float4*>(out);
    #pragma unroll 2
    for (int j = t; j < rows * 4; j += 256) {
        const int l  = row0 + (j >> 2);
        const int c4 = j & 3;
        float4 xv; xv.x = 0.f; xv.y = 0.f; xv.z = 0.f; xv.w = 0.f;
        if (l < L) xv = x4[(b * L + l) * 4 + c4];
        float4 r;
        const int c = c4 * 4;
        r.x = xv.x * sa[c + 0] + sd[c + 0];
        r.y = xv.y * sa[c + 1] + sd[c + 1];
        r.z = xv.z * sa[c + 2] + sd[c + 2];
        r.w = xv.w * sa[c + 3] + sd[c + 3];
        o4[(b * 1535 + l) * 4 + c4] = r;
    }
}

// =====================================================================
extern "C" void kernel_launch(void* const* d_in, const int* in_sizes, int n_in,
                              void* d_out, int out_size) {
    const float* x     = (const float*)d_in[0];
    const float* W1    = (const float*)d_in[1];
    const float* b1    = (const float*)d_in[2];
    const float* W2    = (const float*)d_in[3];
    const float* b2    = (const float*)d_in[4];
    const float* Wl    = (const float*)d_in[5];
    const float* bl    = (const float*)d_in[6];
    const float* Ws    = (const float*)d_in[7];
    const float* bs    = (const float*)d_in[8];
    const float* gamma = (const float*)d_in[9];
    const float* beta  = (const float*)d_in[10];
    const float* mean  = (const float*)d_in[11];
    const float* var   = (const float*)d_in[12];
    float* out = (float*)d_out;

    k_stage1<<<dim3(64, 2), 256>>>(x, W1, b1);
    k_stage2<<<64, 256>>>(W2, b2);
    k_out<<<dim3(16, 12), 256>>>(x, Wl, bl, Ws, bs, gamma, beta, mean, var, out);
}

// round 6
// speedup vs baseline: 2.8996x; 2.8996x over previous
#include <cuda_runtime.h>
#include <math.h>

#define SIZE 512
#define NB 16
#define L 1534
#define NC 16
#define O1 1023
#define O2 512
#define BN_EPS 1e-3f

// ---------------- scratch (no allocations allowed) ----------------
__device__ float g_h1[NB * 1024];            // [b][o] (o padded to 1024)
__device__ float g_h2[NB * O2];              // [b][o2]

// packed fp32x2 FMA (sm_103a FFMA2 path)
__device__ __forceinline__ void ffma2(unsigned long long &acc,
                                      unsigned long long a,
                                      unsigned long long w) {
    asm("fma.rn.f32x2 %0, %1, %2, %0;" : "+l"(acc) : "l"(a), "l"(w));
}

// =====================================================================
// Kernel 1: stage-1, coalesced register-tiled version.
// grid 128 (8-o tiles), block 256 = 8 warps.
// Warp  w: sh = w&3 (4-way s-split, 4 rows each), bg = w>>2 (8 batches).
// Lane  : c4 = lane&3 (float4 channel quad), dr = (lane>>2)&3 (row),
//         bl = lane>>4 (batch LSB).
// Per-thread tile: 8 o x 4 b (x2 b via bl)  -> block covers 8 o x 16 b.
// Every warp-wide load covers contiguous 256B halves (2-3 L1 lines).
// Rows d = sh*4 + dr + 16*i, i = 0..32; i=1..31 are predicate-free.
// =====================================================================
__global__ __launch_bounds__(256, 1) void k_stage1(const float* __restrict__ x,
                                                   const float* __restrict__ W1,
                                                   const float* __restrict__ b1) {
    const int t    = threadIdx.x;
    const int lane = t & 31;
    const int w    = t >> 5;
    const int sh   = w & 3;
    const int bg   = w >> 2;
    const int c4   = lane & 3;
    const int dr   = (lane >> 2) & 3;
    const int bl   = lane >> 4;
    const int o0   = blockIdx.x * 8;

    unsigned long long acc[8][4];
    #pragma unroll
    for (int oo = 0; oo < 8; oo++)
        #pragma unroll
        for (int bb = 0; bb < 4; bb++) acc[oo][bb] = 0ull;

    // weight base: W1[o][s][c] @ o*SIZE*NC + s*NC + c ; s = d - oo, d = d0 + dr
    const float* wb[8];
    #pragma unroll
    for (int oo = 0; oo < 8; oo++) {
        const int og = min(o0 + oo, O1 - 1);          // o=1023 is a dead output
        wb[oo] = W1 + (og * SIZE + dr - oo) * NC + c4 * 4;
    }
    // x base: x[b][r][c] @ (b*L + r)*NC + c ; r = o0 + d0 + dr
    const float* xb[4];
    #pragma unroll
    for (int bb = 0; bb < 4; bb++) {
        const int b = bg * 8 + bb * 2 + bl;
        xb[bb] = x + (b * L + o0 + dr) * NC + c4 * 4;
    }

    // ---- i = 0 : d = sh*4 + dr in [0,16); weight valid iff d >= oo ----
    {
        const int d0 = sh * 4;
        const int d  = d0 + dr;
        ulonglong2 wv[8], xv[4];
        #pragma unroll
        for (int oo = 0; oo < 8; oo++) {
            ulonglong2 z; z.x = 0ull; z.y = 0ull;
            wv[oo] = (d >= oo)
                   ? *reinterpret_cast<const ulonglong2*>(wb[oo] + d0 * NC) : z;
        }
        #pragma unroll
        for (int bb = 0; bb < 4; bb++)
            xv[bb] = *reinterpret_cast<const ulonglong2*>(xb[bb] + d0 * NC);
        #pragma unroll
        for (int oo = 0; oo < 8; oo++)
            #pragma unroll
            for (int bb = 0; bb < 4; bb++) {
                ffma2(acc[oo][bb], xv[bb].x, wv[oo].x);
                ffma2(acc[oo][bb], xv[bb].y, wv[oo].y);
            }
    }

    // ---- i = 1..31 : fully valid, predicate-free ----
    #pragma unroll 4
    for (int i = 1; i < 32; i++) {
        const int off = (sh * 4 + (i << 4)) * NC;
        ulonglong2 wv[8], xv[4];
        #pragma unroll
        for (int oo = 0; oo < 8; oo++)
            wv[oo] = *reinterpret_cast<const ulonglong2*>(wb[oo] + off);
        #pragma unroll
        for (int bb = 0; bb < 4; bb++)
            xv[bb] = *reinterpret_cast<const ulonglong2*>(xb[bb] + off);
        #pragma unroll
        for (int oo = 0; oo < 8; oo++)
            #pragma unroll
            for (int bb = 0; bb < 4; bb++) {
                ffma2(acc[oo][bb], xv[bb].x, wv[oo].x);
                ffma2(acc[oo][bb], xv[bb].y, wv[oo].y);
            }
    }

    // ---- i = 32 : d in [512,520) (sh<2 only); weight valid iff d-oo<=511;
    //      x row may be 1534 (feeds only the dead o=1023 output) ----
    if (sh < 2) {
        const int d0 = sh * 4 + 512;
        const int d  = d0 + dr;
        const bool xok = (o0 + d) < L;
        ulonglong2 wv[8], xv[4];
        #pragma unroll
        for (int oo = 0; oo < 8; oo++) {
            ulonglong2 z; z.x = 0ull; z.y = 0ull;
            wv[oo] = (d - oo <= 511)
                   ? *reinterpret_cast<const ulonglong2*>(wb[oo] + d0 * NC) : z;
        }
        #pragma unroll
        for (int bb = 0; bb < 4; bb++) {
            ulonglong2 z; z.x = 0ull; z.y = 0ull;
            xv[bb] = xok
                   ? *reinterpret_cast<const ulonglong2*>(xb[bb] + d0 * NC) : z;
        }
        #pragma unroll
        for (int oo = 0; oo < 8; oo++)
            #pragma unroll
            for (int bb = 0; bb < 4; bb++) {
                ffma2(acc[oo][bb], xv[bb].x, wv[oo].x);
                ffma2(acc[oo][bb], xv[bb].y, wv[oo].y);
            }
    }

    // ---- reduction: c4 and dr lane dims are both reduction dims ----
    float v[8][4];
    #pragma unroll
    for (int oo = 0; oo < 8; oo++)
        #pragma unroll
        for (int bb = 0; bb < 4; bb++) {
            float2 f = *reinterpret_cast<float2*>(&acc[oo][bb]);
            v[oo][bb] = f.x + f.y;
        }
    #pragma unroll
    for (int mask = 1; mask <= 8; mask <<= 1)
        #pragma unroll
        for (int oo = 0; oo < 8; oo++)
            #pragma unroll
            for (int bb = 0; bb < 4; bb++)
                v[oo][bb] += __shfl_xor_sync(0xffffffffu, v[oo][bb], mask);

    __shared__ float sm[4][2][2][4][8];   // [sh][bg][bl][bb][oo]
    if ((lane & 15) == 0) {
        #pragma unroll
        for (int oo = 0; oo < 8; oo++)
            #pragma unroll
            for (int bb = 0; bb < 4; bb++)
                sm[sh][bg][bl][bb][oo] = v[oo][bb];
    }
    __syncthreads();

    if (t < 128) {
        const int ol  = t >> 4;
        const int b   = t & 15;
        const int bg2 = b >> 3;
        const int bb2 = (b & 7) >> 1;
        const int bl2 = b & 1;
        float s = sm[0][bg2][bl2][bb2][ol] + sm[1][bg2][bl2][bb2][ol]
                + sm[2][bg2][bl2][bb2][ol] + sm[3][bg2][bl2][bb2][ol];
        const int o = o0 + ol;
        if (o < O1) {
            s += b1[o];
            g_h1[b * 1024 + o] = (s > 0.f) ? s : expm1f(s);   // ELU(alpha=1)
        }
    }
}

// =====================================================================
// Kernel 2: stage-2  h2[b,o2] = sum_s h1[b,o2+s] * W2[o2,s] + b2[o2]
// grid 128 (4 o2 per block), block 256 (64-way s split)
// =====================================================================
__global__ __launch_bounds__(256) void k_stage2(const float* __restrict__ W2,
                                                const float* __restrict__ b2) {
    const int t   = threadIdx.x;
    const int ol  = t >> 6;
    const int l64 = t & 63;
    const int o2  = blockIdx.x * 4 + ol;

    float acc[NB];
    #pragma unroll
    for (int b = 0; b < NB; b++) acc[b] = 0.f;

    #pragma unroll
    for (int i = 0; i < 8; i++) {
        const int s = l64 + (i << 6);
        const float w = W2[o2 * SIZE + s];
        #pragma unroll
        for (int b = 0; b < NB; b++)
            acc[b] = fmaf(g_h1[b * 1024 + o2 + s], w, acc[b]);
    }

    __shared__ float red[4 * 64 * 17];
    #pragma unroll
    for (int b = 0; b < NB; b++)
        red[ol * 1088 + l64 * 17 + b] = acc[b];
    __syncthreads();

    if (t < 64) {
        const int olr = t >> 4;
        const int b   = t & 15;
        float s = 0.f;
        #pragma unroll
        for (int j = 0; j < 64; j++)
            s += red[olr * 1088 + j * 17 + b];
        const int o2g = blockIdx.x * 4 + olr;
        g_h2[b * O2 + o2g] = s + b2[o2g];
    }
}

// =====================================================================
// Kernel 3: gate g[b] = (h2.Wl + bl) * sigmoid(h2.Ws + bs), then
// out[b,l,c] = ((xpad + g) - mean)*rsqrt(var+eps)*gamma + beta
// grid (16 b, 12 row-chunks of 128), block 256. Gate recomputed per block.
// =====================================================================
__global__ __launch_bounds__(256) void k_out(const float* __restrict__ x,
                                             const float* __restrict__ Wl,
                                             const float* __restrict__ bl,
                                             const float* __restrict__ Ws,
                                             const float* __restrict__ bs,
                                             const float* __restrict__ gamma,
                                             const float* __restrict__ beta,
                                             const float* __restrict__ mean,
                                             const float* __restrict__ var,
                                             float* __restrict__ out) {
    const int b  = blockIdx.x;
    const int cb = blockIdx.y;
    const int t  = threadIdx.x;

    // gate reduction (512-elem dots, 2 elems/thread)
    float h2a = g_h2[b * O2 + t];
    float h2b = g_h2[b * O2 + 256 + t];
    float aL = h2a * Wl[t] + h2b * Wl[256 + t];
    float aS = h2a * Ws[t] + h2b * Ws[256 + t];
    #pragma unroll
    for (int off = 16; off; off >>= 1) {
        aL += __shfl_down_sync(0xffffffffu, aL, off);
        aS += __shfl_down_sync(0xffffffffu, aS, off);
    }
    __shared__ float rL[8], rS[8];
    __shared__ float sa[16], sd[16];
    __shared__ float gsh;
    if ((t & 31) == 0) { rL[t >> 5] = aL; rS[t >> 5] = aS; }
    __syncthreads();
    if (t == 0) {
        float sL = 0.f, sS = 0.f;
        #pragma unroll
        for (int j = 0; j < 8; j++) { sL += rL[j]; sS += rS[j]; }
        sL += bl[0]; sS += bs[0];
        gsh = sL * (1.f / (1.f + expf(-sS)));
    }
    __syncthreads();
    if (t < 16) {
        float sc = gamma[t] * rsqrtf(var[t] + BN_EPS);
        sa[t] = sc;
        sd[t] = beta[t] - mean[t] * sc + gsh * sc;   // folds gate + BN shift
    }
    __syncthreads();

    const int row0 = cb * 128;
    const int rows = min(128, 1535 - row0);
    const float4* x4 = reinterpret_cast<const float4*>(x);
    float4* o4 = reinterpret_cast<float4*>(out);
    #pragma unroll 2
    for (int j = t; j < rows * 4; j += 256) {
        const int l  = row0 + (j >> 2);
        const int c4 = j & 3;
        float4 xv; xv.x = 0.f; xv.y = 0.f; xv.z = 0.f; xv.w = 0.f;
        if (l < L) xv = x4[(b * L + l) * 4 + c4];
        float4 r;
        const int c = c4 * 4;
        r.x = xv.x * sa[c + 0] + sd[c + 0];
        r.y = xv.y * sa[c + 1] + sd[c + 1];
        r.z = xv.z * sa[c + 2] + sd[c + 2];
        r.w = xv.w * sa[c + 3] + sd[c + 3];
        o4[(b * 1535 + l) * 4 + c4] = r;
    }
}

// =====================================================================
extern "C" void kernel_launch(void* const* d_in, const int* in_sizes, int n_in,
                              void* d_out, int out_size) {
    const float* x     = (const float*)d_in[0];
    const float* W1    = (const float*)d_in[1];
    const float* b1    = (const float*)d_in[2];
    const float* W2    = (const float*)d_in[3];
    const float* b2    = (const float*)d_in[4];
    const float* Wl    = (const float*)d_in[5];
    const float* bl    = (const float*)d_in[6];
    const float* Ws    = (const float*)d_in[7];
    const float* bs    = (const float*)d_in[8];
    const float* gamma = (const float*)d_in[9];
    const float* beta  = (const float*)d_in[10];
    const float* mean  = (const float*)d_in[11];
    const float* var   = (const float*)d_in[12];
    float* out = (float*)d_out;

    k_stage1<<<128, 256>>>(x, W1, b1);
    k_stage2<<<128, 256>>>(W2, b2);
    k_out<<<dim3(16, 12), 256>>>(x, Wl, bl, Ws, bs, gamma, beta, mean, var, out);
}